// round 1
// baseline (speedup 1.0000x reference)
#include <cuda_runtime.h>
#include <math.h>

#define HH 512
#define WW 512
#define HW (512*512)
#define NORG 10
#define SS 32
#define NPART 64
#define CHUNK (HW/NPART)   // 4096

// Output layout (flattened reference tuple, fp32):
//   [0, 2*HW)            size map  = abs(int32(features[1025:1027]))
//   [2*HW, 2*HW+20)      centers   = (px, py) per organ
//   [2*HW+20, +10*HW)    final mask
#define SIZE_BASE 0
#define CEN_BASE  (2*HW)
#define FIN_BASE  (2*HW + 2*NORG)

// ---- scratch (no allocations allowed) ----
__device__ float g_pval[NORG*NPART];
__device__ int   g_pidx[NORG*NPART];
__device__ int   g_r0[NORG], g_c0[NORG], g_sh[NORG], g_sw[NORG];
__device__ float g_shape[NORG*SS*SS];

__device__ __forceinline__ void better(float v, int i, float& bv, int& bi) {
    if (v > bv || (v == bv && i < bi)) { bv = v; bi = i; }
}

// ---------------- Kernel 1: argmax partials over heat ----------------
__global__ void argmax_stage1(const float* __restrict__ f) {
    int o = blockIdx.x / NPART;
    int b = blockIdx.x % NPART;
    const float4* heat = (const float4*)(f + (size_t)(1027 + o) * HW + (size_t)b * CHUNK);
    int tid = threadIdx.x;

    float bv = -INFINITY; int bi = 0x7fffffff;
    int base = b * CHUNK;
    // 4096 elems = 1024 float4; 256 threads -> 4 each, ascending order per thread
    #pragma unroll
    for (int j = tid; j < CHUNK/4; j += 256) {
        float4 v = heat[j];
        int i0 = base + j*4;
        better(v.x, i0+0, bv, bi);
        better(v.y, i0+1, bv, bi);
        better(v.z, i0+2, bv, bi);
        better(v.w, i0+3, bv, bi);
    }
    __shared__ float sv[256];
    __shared__ int   si[256];
    sv[tid] = bv; si[tid] = bi;
    __syncthreads();
    for (int s = 128; s > 0; s >>= 1) {
        if (tid < s) better(sv[tid+s], si[tid+s], sv[tid], si[tid]);
        __syncthreads();
    }
    if (tid == 0) { g_pval[blockIdx.x] = sv[0]; g_pidx[blockIdx.x] = si[0]; }
}

// ---------- Kernel 2: finish argmax, compute params, gather shape ----------
__global__ void finalize_gather(const float* __restrict__ f, float* __restrict__ out) {
    int o = blockIdx.x;
    int tid = threadIdx.x;
    __shared__ float sv[NPART];
    __shared__ int   si[NPART];
    __shared__ int   sidx;

    if (tid < NPART) { sv[tid] = g_pval[o*NPART + tid]; si[tid] = g_pidx[o*NPART + tid]; }
    __syncthreads();
    for (int s = NPART/2; s > 0; s >>= 1) {
        if (tid < s) better(sv[tid+s], si[tid+s], sv[tid], si[tid]);
        __syncthreads();
    }
    if (tid == 0) {
        int idx = si[0];
        sidx = idx;
        int py = idx / WW, px = idx % WW;
        int v0 = (int)f[(size_t)1025*HW + idx]; if (v0 < 0) v0 = -v0;
        int v1 = (int)f[(size_t)1026*HW + idx]; if (v1 < 0) v1 = -v1;
        int sh = v0 > 1 ? v0 : 1;
        int sw = v1 > 1 ? v1 : 1;
        g_sh[o] = sh; g_sw[o] = sw;
        g_r0[o] = py - sh/2;
        g_c0[o] = px - sw/2;
        out[CEN_BASE + o*2 + 0] = (float)px;
        out[CEN_BASE + o*2 + 1] = (float)py;
    }
    __syncthreads();
    int idx = sidx;
    // gather the 1024 shape logits at the peak location (channels 1..1024)
    for (int c = tid; c < SS*SS; c += blockDim.x)
        g_shape[o*SS*SS + c] = f[(size_t)(1 + c)*HW + idx];
}

// ---------------- Kernel 3: size map (elementwise) ----------------
__global__ void size_map(const float* __restrict__ f, float* __restrict__ out) {
    int i = blockIdx.x * blockDim.x + threadIdx.x;   // over 2*HW/4 float4s
    const float4* src = (const float4*)(f + (size_t)1025*HW);
    float4 v = src[i];
    int a0 = (int)v.x; if (a0 < 0) a0 = -a0;
    int a1 = (int)v.y; if (a1 < 0) a1 = -a1;
    int a2 = (int)v.z; if (a2 < 0) a2 = -a2;
    int a3 = (int)v.w; if (a3 < 0) a3 = -a3;
    float4 r = make_float4((float)a0, (float)a1, (float)a2, (float)a3);
    ((float4*)(out + SIZE_BASE))[i] = r;
}

__device__ __forceinline__ float sigmoidf_(float x) {
    return 1.0f / (1.0f + __expf(-x));
}

// ---------------- Kernel 4: final mask ----------------
// grid (W/128, H/2, NORG), block (128, 2)
__global__ void final_mask(const float* __restrict__ f, float* __restrict__ out) {
    int o = blockIdx.z;
    int c_base = blockIdx.x * 128;
    int r_base = blockIdx.y * 2;
    int c = c_base + threadIdx.x;
    int r = r_base + threadIdx.y;
    float* op = out + FIN_BASE + (size_t)o * HW;

    int r0 = g_r0[o], c0 = g_c0[o], sh = g_sh[o], sw = g_sw[o];

    // whole-tile miss -> zero fill, skip smem load (uniform branch)
    if (r_base + 2 <= r0 || r_base >= r0 + sh || c_base + 128 <= c0 || c_base >= c0 + sw) {
        op[r*WW + c] = 0.0f;
        return;
    }

    __shared__ float s[SS*SS];
    int tid = threadIdx.y * 128 + threadIdx.x;
    for (int i = tid; i < SS*SS; i += 256) s[i] = g_shape[o*SS*SS + i];
    __syncthreads();

    float v = 0.0f;
    if (r >= r0 && r < r0 + sh && c >= c0 && c < c0 + sw) {
        float sy = ((float)(r - r0) + 0.5f) * ((float)SS / (float)sh) - 0.5f;
        float sx = ((float)(c - c0) + 0.5f) * ((float)SS / (float)sw) - 0.5f;
        sy = fminf(fmaxf(sy, 0.0f), (float)(SS - 1));
        sx = fminf(fmaxf(sx, 0.0f), (float)(SS - 1));
        int y0 = (int)floorf(sy), x0 = (int)floorf(sx);
        int y1 = min(y0 + 1, SS - 1), x1 = min(x0 + 1, SS - 1);
        float wy = sy - (float)y0, wx = sx - (float)x0;
        float v00 = s[y0*SS + x0], v01 = s[y0*SS + x1];
        float v10 = s[y1*SS + x0], v11 = s[y1*SS + x1];
        float loc = (1.0f - wy) * ((1.0f - wx)*v00 + wx*v01)
                  +          wy * ((1.0f - wx)*v10 + wx*v11);
        float sal = f[(size_t)r*WW + c];   // channel 0
        v = sigmoidf_(loc) * sigmoidf_(sal);
    }
    op[r*WW + c] = v;
}

extern "C" void kernel_launch(void* const* d_in, const int* in_sizes, int n_in,
                              void* d_out, int out_size) {
    const float* f = (const float*)d_in[0];
    float* out = (float*)d_out;
    (void)in_sizes; (void)n_in; (void)out_size;

    argmax_stage1<<<NORG*NPART, 256>>>(f);
    finalize_gather<<<NORG, 256>>>(f, out);
    size_map<<<(2*HW/4)/256, 256>>>(f, out);
    final_mask<<<dim3(WW/128, HH/2, NORG), dim3(128, 2)>>>(f, out);
}

// round 2
// speedup vs baseline: 1.2521x; 1.2521x over previous
#include <cuda_runtime.h>
#include <math.h>

#define HH 512
#define WW 512
#define HW (512*512)
#define NORG 10
#define SS 32
#define NPART 64
#define CHUNK (HW/NPART)   // 4096

// Output layout (flattened reference tuple, fp32):
//   [0, 2*HW)            size map  = abs(int32(features[1025:1027]))
//   [2*HW, 2*HW+20)      centers   = (px, py) per organ
//   [2*HW+20, +10*HW)    final mask
#define SIZE_BASE 0
#define CEN_BASE  (2*HW)
#define FIN_BASE  (2*HW + 2*NORG)

// ---- scratch (no allocations allowed) ----
__device__ float g_pval[NORG*NPART];
__device__ int   g_pidx[NORG*NPART];
__device__ int4  g_box[NORG];            // (r0, c0, sh, sw)
__device__ float g_shape[NORG*SS*SS];

__device__ __forceinline__ void better(float v, int i, float& bv, int& bi) {
    if (v > bv || (v == bv && i < bi)) { bv = v; bi = i; }
}

// ---------------- Kernel 1: argmax partials over heat ----------------
__global__ void argmax_stage1(const float* __restrict__ f) {
    int o = blockIdx.x / NPART;
    int b = blockIdx.x % NPART;
    const float4* heat = (const float4*)(f + (size_t)(1027 + o) * HW + (size_t)b * CHUNK);
    int tid = threadIdx.x;

    float bv = -INFINITY; int bi = 0x7fffffff;
    int base = b * CHUNK;
    // 4096 elems = 1024 float4; 256 threads -> 4 independent float4 each
    #pragma unroll
    for (int j = tid; j < CHUNK/4; j += 256) {
        float4 v = heat[j];
        int i0 = base + j*4;
        better(v.x, i0+0, bv, bi);
        better(v.y, i0+1, bv, bi);
        better(v.z, i0+2, bv, bi);
        better(v.w, i0+3, bv, bi);
    }
    __shared__ float sv[256];
    __shared__ int   si[256];
    sv[tid] = bv; si[tid] = bi;
    __syncthreads();
    for (int s = 128; s > 0; s >>= 1) {
        if (tid < s) better(sv[tid+s], si[tid+s], sv[tid], si[tid]);
        __syncthreads();
    }
    if (tid == 0) { g_pval[blockIdx.x] = sv[0]; g_pidx[blockIdx.x] = si[0]; }
}

// ---------- Kernel 2: finish argmax, compute params, gather shape ----------
__global__ void finalize_gather(const float* __restrict__ f, float* __restrict__ out) {
    int o = blockIdx.x;
    int tid = threadIdx.x;
    __shared__ float sv[NPART];
    __shared__ int   si[NPART];
    __shared__ int   sidx;

    if (tid < NPART) { sv[tid] = g_pval[o*NPART + tid]; si[tid] = g_pidx[o*NPART + tid]; }
    __syncthreads();
    for (int s = NPART/2; s > 0; s >>= 1) {
        if (tid < s) better(sv[tid+s], si[tid+s], sv[tid], si[tid]);
        __syncthreads();
    }
    if (tid == 0) {
        int idx = si[0];
        sidx = idx;
        int py = idx / WW, px = idx % WW;
        int v0 = (int)f[(size_t)1025*HW + idx]; if (v0 < 0) v0 = -v0;
        int v1 = (int)f[(size_t)1026*HW + idx]; if (v1 < 0) v1 = -v1;
        int sh = v0 > 1 ? v0 : 1;
        int sw = v1 > 1 ? v1 : 1;
        g_box[o] = make_int4(py - sh/2, px - sw/2, sh, sw);
        out[CEN_BASE + o*2 + 0] = (float)px;
        out[CEN_BASE + o*2 + 1] = (float)py;
    }
    __syncthreads();
    int idx = sidx;
    // gather the 1024 shape logits at the peak location (channels 1..1024)
    for (int c = tid; c < SS*SS; c += blockDim.x)
        g_shape[o*SS*SS + c] = f[(size_t)(1 + c)*HW + idx];
}

__device__ __forceinline__ float sigmoidf_(float x) {
    return 1.0f / (1.0f + __expf(-x));
}

// ------------- Kernel 3: fused size map + final mask --------------
// grid (1, 256, NORG+1), block 256.
//   z <  NORG : final mask, block = 2 full rows (1024 px), 1 float4/thread
//   z == NORG : size map, 512 float4 per block, 2 float4/thread
__global__ void fused_out(const float* __restrict__ f, float* __restrict__ out) {
    int z = blockIdx.z;
    int tid = threadIdx.x;

    if (z == NORG) {
        const float4* src = (const float4*)(f + (size_t)1025*HW);
        float4* dst = (float4*)(out + SIZE_BASE);
        int base = blockIdx.y * 512 + tid;
        #pragma unroll
        for (int k = 0; k < 2; k++) {
            int i = base + k*256;
            float4 v = src[i];
            int a0 = (int)v.x; if (a0 < 0) a0 = -a0;
            int a1 = (int)v.y; if (a1 < 0) a1 = -a1;
            int a2 = (int)v.z; if (a2 < 0) a2 = -a2;
            int a3 = (int)v.w; if (a3 < 0) a3 = -a3;
            dst[i] = make_float4((float)a0, (float)a1, (float)a2, (float)a3);
        }
        return;
    }

    int o = z;
    int r_base = blockIdx.y * 2;
    int row = r_base + (tid >> 7);          // 2 rows per block
    int cb  = (tid & 127) * 4;              // first of 4 columns
    float4* orow = (float4*)(out + FIN_BASE + (size_t)o * HW + (size_t)row * WW);

    int4 box = g_box[o];                    // single LDG.128
    int r0 = box.x, c0 = box.y, sh = box.z, sw = box.w;

    // whole-stripe miss (column overlap with full-width stripe is always nonempty)
    if (r_base + 2 <= r0 || r_base >= r0 + sh) {
        orow[tid & 127] = make_float4(0.f, 0.f, 0.f, 0.f);
        return;
    }

    __shared__ float s[SS*SS];
    for (int i = tid; i < SS*SS; i += 256) s[i] = g_shape[o*SS*SS + i];
    __syncthreads();

    float res[4] = {0.f, 0.f, 0.f, 0.f};
    bool rin = (row >= r0) && (row < r0 + sh);
    if (rin && cb + 4 > c0 && cb < c0 + sw) {
        // row-constant bilinear terms
        float sy = ((float)(row - r0) + 0.5f) * ((float)SS / (float)sh) - 0.5f;
        sy = fminf(fmaxf(sy, 0.0f), (float)(SS - 1));
        int y0 = (int)floorf(sy);
        int y1 = min(y0 + 1, SS - 1);
        float wy = sy - (float)y0;
        const float* sr0 = s + y0*SS;
        const float* sr1 = s + y1*SS;
        #pragma unroll
        for (int j = 0; j < 4; j++) {
            int c = cb + j;
            if (c >= c0 && c < c0 + sw) {
                float sx = ((float)(c - c0) + 0.5f) * ((float)SS / (float)sw) - 0.5f;
                sx = fminf(fmaxf(sx, 0.0f), (float)(SS - 1));
                int x0 = (int)floorf(sx);
                int x1 = min(x0 + 1, SS - 1);
                float wx = sx - (float)x0;
                float top = (1.0f - wx)*sr0[x0] + wx*sr0[x1];
                float bot = (1.0f - wx)*sr1[x0] + wx*sr1[x1];
                float loc = (1.0f - wy)*top + wy*bot;
                float sal = f[(size_t)row*WW + c];   // channel 0
                res[j] = sigmoidf_(loc) * sigmoidf_(sal);
            }
        }
    }
    orow[tid & 127] = make_float4(res[0], res[1], res[2], res[3]);
}

extern "C" void kernel_launch(void* const* d_in, const int* in_sizes, int n_in,
                              void* d_out, int out_size) {
    const float* f = (const float*)d_in[0];
    float* out = (float*)d_out;
    (void)in_sizes; (void)n_in; (void)out_size;

    argmax_stage1<<<NORG*NPART, 256>>>(f);
    finalize_gather<<<NORG, 256>>>(f, out);
    fused_out<<<dim3(1, HH/2, NORG+1), 256>>>(f, out);
}

// round 3
// speedup vs baseline: 1.2548x; 1.0021x over previous
#include <cuda_runtime.h>
#include <math.h>

#define HH 512
#define WW 512
#define HW (512*512)
#define NORG 10
#define SS 32
#define NPART 64
#define CHUNK (HW/NPART)   // 4096

// Output layout (flattened reference tuple, fp32):
//   [0, 2*HW)            size map  = abs(int32(features[1025:1027]))
//   [2*HW, 2*HW+20)      centers   = (px, py) per organ
//   [2*HW+20, +10*HW)    final mask
#define SIZE_BASE 0
#define CEN_BASE  (2*HW)
#define FIN_BASE  (2*HW + 2*NORG)

// ---- scratch (no allocations allowed) ----
__device__ float g_pval[NORG*NPART];
__device__ int   g_pidx[NORG*NPART];
__device__ int4  g_box[NORG];            // (r0, c0, sh, sw)
__device__ float g_shape[NORG*SS*SS];

__device__ __forceinline__ void better(float v, int i, float& bv, int& bi) {
    if (v > bv || (v == bv && i < bi)) { bv = v; bi = i; }
}

// ---------------- Kernel 1: argmax partials over heat ----------------
// Loads are explicitly batched (4x LDG.128 per thread in flight) BEFORE any
// comparison, so the (bv,bi) serial chain can't throttle MLP to 1.
__global__ void argmax_stage1(const float* __restrict__ f) {
    int o = blockIdx.x >> 6;          // / NPART
    int b = blockIdx.x & 63;          // % NPART
    const float4* heat = (const float4*)(f + (size_t)(1027 + o) * HW + (size_t)b * CHUNK);
    int tid = threadIdx.x;

    float4 v[4];
    #pragma unroll
    for (int k = 0; k < 4; k++) v[k] = heat[tid + k*256];

    float bv = -INFINITY; int bi = 0x7fffffff;
    int base = b * CHUNK;
    #pragma unroll
    for (int k = 0; k < 4; k++) {
        // 3-op max tree; index work only on (rare) improvement
        float m = fmaxf(fmaxf(v[k].x, v[k].y), fmaxf(v[k].z, v[k].w));
        if (m > bv) {
            bv = m;
            int j = base + (tid + k*256) * 4;
            if      (v[k].x == m) bi = j;
            else if (v[k].y == m) bi = j + 1;
            else if (v[k].z == m) bi = j + 2;
            else                  bi = j + 3;
        }
    }

    // warp reduction (lexicographic: max value, then min index)
    #pragma unroll
    for (int s = 16; s > 0; s >>= 1) {
        float ov = __shfl_down_sync(0xffffffffu, bv, s);
        int   oi = __shfl_down_sync(0xffffffffu, bi, s);
        better(ov, oi, bv, bi);
    }

    __shared__ float sv[8];
    __shared__ int   si[8];
    if ((tid & 31) == 0) { sv[tid >> 5] = bv; si[tid >> 5] = bi; }
    __syncthreads();
    if (tid == 0) {
        #pragma unroll
        for (int w = 1; w < 8; w++) better(sv[w], si[w], sv[0], si[0]);
        g_pval[blockIdx.x] = sv[0];
        g_pidx[blockIdx.x] = si[0];
    }
}

// ---------- Kernel 2: finish argmax, compute params, gather shape ----------
__global__ void finalize_gather(const float* __restrict__ f, float* __restrict__ out) {
    int o = blockIdx.x;
    int tid = threadIdx.x;
    __shared__ float sv[NPART];
    __shared__ int   si[NPART];
    __shared__ int   sidx;

    if (tid < NPART) { sv[tid] = g_pval[o*NPART + tid]; si[tid] = g_pidx[o*NPART + tid]; }
    __syncthreads();
    for (int s = NPART/2; s > 0; s >>= 1) {
        if (tid < s) better(sv[tid+s], si[tid+s], sv[tid], si[tid]);
        __syncthreads();
    }
    if (tid == 0) {
        int idx = si[0];
        sidx = idx;
        int py = idx / WW, px = idx % WW;
        int v0 = (int)f[(size_t)1025*HW + idx]; if (v0 < 0) v0 = -v0;
        int v1 = (int)f[(size_t)1026*HW + idx]; if (v1 < 0) v1 = -v1;
        int sh = v0 > 1 ? v0 : 1;
        int sw = v1 > 1 ? v1 : 1;
        g_box[o] = make_int4(py - sh/2, px - sw/2, sh, sw);
        out[CEN_BASE + o*2 + 0] = (float)px;
        out[CEN_BASE + o*2 + 1] = (float)py;
    }
    __syncthreads();
    int idx = sidx;
    // gather the 1024 shape logits at the peak location (channels 1..1024)
    for (int c = tid; c < SS*SS; c += blockDim.x)
        g_shape[o*SS*SS + c] = f[(size_t)(1 + c)*HW + idx];
}

__device__ __forceinline__ float sigmoidf_(float x) {
    return 1.0f / (1.0f + __expf(-x));
}

// ------------- Kernel 3: fused size map + final mask --------------
// grid (1, 256, NORG+1), block 256.
//   z <  NORG : final mask, block = 2 full rows (1024 px), 1 float4/thread
//   z == NORG : size map, 512 float4 per block, 2 float4/thread
__global__ void fused_out(const float* __restrict__ f, float* __restrict__ out) {
    int z = blockIdx.z;
    int tid = threadIdx.x;

    if (z == NORG) {
        const float4* src = (const float4*)(f + (size_t)1025*HW);
        float4* dst = (float4*)(out + SIZE_BASE);
        int base = blockIdx.y * 512 + tid;
        #pragma unroll
        for (int k = 0; k < 2; k++) {
            int i = base + k*256;
            float4 v = src[i];
            int a0 = (int)v.x; if (a0 < 0) a0 = -a0;
            int a1 = (int)v.y; if (a1 < 0) a1 = -a1;
            int a2 = (int)v.z; if (a2 < 0) a2 = -a2;
            int a3 = (int)v.w; if (a3 < 0) a3 = -a3;
            dst[i] = make_float4((float)a0, (float)a1, (float)a2, (float)a3);
        }
        return;
    }

    int o = z;
    int r_base = blockIdx.y * 2;
    int row = r_base + (tid >> 7);          // 2 rows per block
    int cb  = (tid & 127) * 4;              // first of 4 columns
    float4* orow = (float4*)(out + FIN_BASE + (size_t)o * HW + (size_t)row * WW);

    int4 box = g_box[o];                    // single LDG.128
    int r0 = box.x, c0 = box.y, sh = box.z, sw = box.w;

    // whole-stripe miss (column overlap with full-width stripe is always nonempty)
    if (r_base + 2 <= r0 || r_base >= r0 + sh) {
        orow[tid & 127] = make_float4(0.f, 0.f, 0.f, 0.f);
        return;
    }

    __shared__ float s[SS*SS];
    for (int i = tid; i < SS*SS; i += 256) s[i] = g_shape[o*SS*SS + i];
    __syncthreads();

    float res[4] = {0.f, 0.f, 0.f, 0.f};
    bool rin = (row >= r0) && (row < r0 + sh);
    if (rin && cb + 4 > c0 && cb < c0 + sw) {
        // row-constant bilinear terms
        float sy = ((float)(row - r0) + 0.5f) * ((float)SS / (float)sh) - 0.5f;
        sy = fminf(fmaxf(sy, 0.0f), (float)(SS - 1));
        int y0 = (int)floorf(sy);
        int y1 = min(y0 + 1, SS - 1);
        float wy = sy - (float)y0;
        const float* sr0 = s + y0*SS;
        const float* sr1 = s + y1*SS;
        #pragma unroll
        for (int j = 0; j < 4; j++) {
            int c = cb + j;
            if (c >= c0 && c < c0 + sw) {
                float sx = ((float)(c - c0) + 0.5f) * ((float)SS / (float)sw) - 0.5f;
                sx = fminf(fmaxf(sx, 0.0f), (float)(SS - 1));
                int x0 = (int)floorf(sx);
                int x1 = min(x0 + 1, SS - 1);
                float wx = sx - (float)x0;
                float top = (1.0f - wx)*sr0[x0] + wx*sr0[x1];
                float bot = (1.0f - wx)*sr1[x0] + wx*sr1[x1];
                float loc = (1.0f - wy)*top + wy*bot;
                float sal = f[(size_t)row*WW + c];   // channel 0
                res[j] = sigmoidf_(loc) * sigmoidf_(sal);
            }
        }
    }
    orow[tid & 127] = make_float4(res[0], res[1], res[2], res[3]);
}

extern "C" void kernel_launch(void* const* d_in, const int* in_sizes, int n_in,
                              void* d_out, int out_size) {
    const float* f = (const float*)d_in[0];
    float* out = (float*)d_out;
    (void)in_sizes; (void)n_in; (void)out_size;

    argmax_stage1<<<NORG*NPART, 256>>>(f);
    finalize_gather<<<NORG, 256>>>(f, out);
    fused_out<<<dim3(1, HH/2, NORG+1), 256>>>(f, out);
}